// round 2
// baseline (speedup 1.0000x reference)
#include <cuda_runtime.h>
#include <cuda_bf16.h>
#include <cstdint>

// ============================================================================
// Problem constants
// ============================================================================
#define DFEAT 128
#define N_DST_MAX 100000

// agg scratch: [N_DST, 128] fp32 (51.2 MB) — static device array (no alloc)
__device__ __align__(16) float g_agg[(size_t)N_DST_MAX * DFEAT];

// ============================================================================
// Helpers
// ============================================================================
__device__ __forceinline__ uint32_t smem_to_u32(const void* smem_ptr) {
    uint32_t addr;
    asm("{ .reg .u64 tmp; cvta.to.shared.u64 tmp, %1; cvt.u32.u64 %0, tmp; }"
        : "=r"(addr) : "l"(smem_ptr));
    return addr;
}

#define LDSM_X4(r, addr) \
    asm volatile("ldmatrix.sync.aligned.m8n8.x4.shared.b16 {%0,%1,%2,%3}, [%4];" \
        : "=r"((r)[0]), "=r"((r)[1]), "=r"((r)[2]), "=r"((r)[3]) : "r"(addr))

#define MMA_BF16(d, a, b0, b1) \
    asm volatile("mma.sync.aligned.m16n8k16.row.col.f32.bf16.bf16.f32 " \
        "{%0,%1,%2,%3}, {%4,%5,%6,%7}, {%8,%9}, {%0,%1,%2,%3};" \
        : "+f"((d)[0]), "+f"((d)[1]), "+f"((d)[2]), "+f"((d)[3]) \
        : "r"((a)[0]), "r"((a)[1]), "r"((a)[2]), "r"((a)[3]), "r"(b0), "r"(b1))

__device__ __forceinline__ void split2(float f0, float f1, uint32_t& hi, uint32_t& lo) {
    __nv_bfloat16 h0 = __float2bfloat16(f0);
    __nv_bfloat16 h1 = __float2bfloat16(f1);
    __nv_bfloat16 l0 = __float2bfloat16(f0 - __bfloat162float(h0));
    __nv_bfloat16 l1 = __float2bfloat16(f1 - __bfloat162float(h1));
    hi = ((uint32_t)__bfloat16_as_ushort(h1) << 16) | (uint32_t)__bfloat16_as_ushort(h0);
    lo = ((uint32_t)__bfloat16_as_ushort(l1) << 16) | (uint32_t)__bfloat16_as_ushort(l0);
}

// ============================================================================
// Kernel 0: zero the agg scratch
// ============================================================================
__global__ void zero_agg_kernel(int n4) {
    int i = blockIdx.x * blockDim.x + threadIdx.x;
    if (i < n4) reinterpret_cast<float4*>(g_agg)[i] = make_float4(0.f, 0.f, 0.f, 0.f);
}

// ============================================================================
// Kernel 1: edge scatter  agg[dst] += x[src]
// One warp per edge; each lane handles a float4; vector red to L2.
// ============================================================================
__global__ void __launch_bounds__(256) scatter_kernel(
    const float* __restrict__ x,
    const int* __restrict__ src_idx,
    const int* __restrict__ dst_idx,
    int n_edge)
{
    int t = blockIdx.x * blockDim.x + threadIdx.x;
    int e = t >> 5;
    if (e >= n_edge) return;
    int lane = t & 31;
    int s = __ldg(src_idx + e);
    int d = __ldg(dst_idx + e);
    float4 v = __ldg(reinterpret_cast<const float4*>(x + (size_t)s * DFEAT) + lane);
    float* p = g_agg + (size_t)d * DFEAT + lane * 4;
    asm volatile("red.global.add.v4.f32 [%0], {%1, %2, %3, %4};"
                 :: "l"(p), "f"(v.x), "f"(v.y), "f"(v.z), "f"(v.w) : "memory");
}

// ============================================================================
// Kernel 2: fused GEMM via mma.sync bf16 + hi/lo 3-term split
//   out[r,:] = (agg[r,:]/deg[r]) @ W1^T + x[self_ids[r],:] @ W2^T
// CTA: 256 threads (8 warps, 4x2), output tile 128x128, warp tile 32x64.
// K processed in two 128-blocks (kb=0: agg vs W1, kb=1: x[self] vs W2).
// Per kb, 3 passes: Ah*Bh + Al*Bh + Ah*Bl  (fp32 accum in registers).
// ============================================================================
// smem: 4 tiles of 128 rows x 136 bf16 (pitch 272B = 17*16B -> ldmatrix
// conflict-free without swizzle)
#define ROWPITCH 272
#define TILE_BYTES (128 * ROWPITCH)  // 34816
#define SM_A_HI 0
#define SM_A_LO (TILE_BYTES)
#define SM_B_HI (2 * TILE_BYTES)
#define SM_B_LO (3 * TILE_BYTES)
#define SMEM_TOTAL (4 * TILE_BYTES)  // 139264

__global__ void __launch_bounds__(256, 1) fused_gemm_kernel(
    const float* __restrict__ x,
    const float* __restrict__ W1,
    const float* __restrict__ W2,
    const float* __restrict__ degree,
    const int* __restrict__ self_ids,
    float* __restrict__ out,
    int n_dst)
{
    extern __shared__ char smem[];
    uint32_t smem_base = smem_to_u32(smem);
    int tid = threadIdx.x;
    int wid = tid >> 5;
    int lane = tid & 31;
    int tile = blockIdx.x;

    int warp_m = (wid & 3) * 32;   // 0,32,64,96
    int warp_n = (wid >> 2) * 64;  // 0,64

    float acc[2][8][4];
    #pragma unroll
    for (int i = 0; i < 2; i++)
        #pragma unroll
        for (int j = 0; j < 8; j++)
            #pragma unroll
            for (int q = 0; q < 4; q++) acc[i][j][q] = 0.f;

    // per-lane ldmatrix base offsets (bytes), independent of k-step / frag
    // A: matrices order (m0-7,k0)(m8-15,k0)(m0-7,k8)(m8-15,k8)
    uint32_t aoff = (uint32_t)(warp_m + (lane & 15)) * ROWPITCH
                  + ((lane & 16) ? 16u : 0u);  // +8 bf16 = 16B for k-high half
    // B: matrices order (n0-7,k0)(n0-7,k8)(n8-15,k0)(n8-15,k8)
    uint32_t boff = (uint32_t)(warp_n + (lane & 7) + ((lane & 16) ? 8 : 0)) * ROWPITCH
                  + ((lane & 8) ? 16u : 0u);

    // tile-load thread mapping: row = tid/2, half-row of 64 floats
    int lrow = tid >> 1;
    int lcol = (tid & 1) * 64;

    #pragma unroll
    for (int kb = 0; kb < 2; kb++) {
        if (kb) __syncthreads();  // previous mma reads done before overwrite

        // ---- load A half-tile (agg/deg for kb=0, x[self] for kb=1) ----
        {
            int r = tile * 128 + lrow;
            const float4* src = nullptr;
            float scale = 1.f;
            if (r < n_dst) {
                if (kb == 0) {
                    src = reinterpret_cast<const float4*>(g_agg + (size_t)r * DFEAT + lcol);
                    scale = 1.0f / __ldg(degree + r);
                } else {
                    int sid = __ldg(self_ids + r);
                    src = reinterpret_cast<const float4*>(x + (size_t)sid * DFEAT + lcol);
                }
            }
            #pragma unroll
            for (int j = 0; j < 16; j++) {
                float4 v = make_float4(0.f, 0.f, 0.f, 0.f);
                if (src) {
                    v = __ldg(src + j);
                    v.x *= scale; v.y *= scale; v.z *= scale; v.w *= scale;
                }
                uint32_t h0, l0, h1, l1;
                split2(v.x, v.y, h0, l0);
                split2(v.z, v.w, h1, l1);
                uint32_t o = (uint32_t)lrow * ROWPITCH + (uint32_t)(lcol + 4 * j) * 2;
                *reinterpret_cast<uint32_t*>(smem + SM_A_HI + o)     = h0;
                *reinterpret_cast<uint32_t*>(smem + SM_A_HI + o + 4) = h1;
                *reinterpret_cast<uint32_t*>(smem + SM_A_LO + o)     = l0;
                *reinterpret_cast<uint32_t*>(smem + SM_A_LO + o + 4) = l1;
            }
        }
        // ---- load B half-tile (W1 for kb=0, W2 for kb=1), layout [n][k] ----
        {
            const float* W = kb ? W2 : W1;
            const float4* src = reinterpret_cast<const float4*>(
                W + (size_t)lrow * DFEAT + lcol);
            #pragma unroll
            for (int j = 0; j < 16; j++) {
                float4 v = __ldg(src + j);
                uint32_t h0, l0, h1, l1;
                split2(v.x, v.y, h0, l0);
                split2(v.z, v.w, h1, l1);
                uint32_t o = (uint32_t)lrow * ROWPITCH + (uint32_t)(lcol + 4 * j) * 2;
                *reinterpret_cast<uint32_t*>(smem + SM_B_HI + o)     = h0;
                *reinterpret_cast<uint32_t*>(smem + SM_B_HI + o + 4) = h1;
                *reinterpret_cast<uint32_t*>(smem + SM_B_LO + o)     = l0;
                *reinterpret_cast<uint32_t*>(smem + SM_B_LO + o + 4) = l1;
            }
        }
        __syncthreads();

        // ---- 3 passes x 8 k-steps of mma ----
        #pragma unroll
        for (int p = 0; p < 3; p++) {
            uint32_t abase = smem_base + (p == 1 ? SM_A_LO : SM_A_HI) + aoff;
            uint32_t bbase = smem_base + (p == 2 ? SM_B_LO : SM_B_HI) + boff;
            #pragma unroll
            for (int ks = 0; ks < 8; ks++) {
                uint32_t a0r[4], a1r[4];
                LDSM_X4(a0r, abase + ks * 32);
                LDSM_X4(a1r, abase + 16 * ROWPITCH + ks * 32);
                #pragma unroll
                for (int nf2 = 0; nf2 < 4; nf2++) {
                    uint32_t br[4];
                    LDSM_X4(br, bbase + nf2 * 16 * ROWPITCH + ks * 32);
                    MMA_BF16(acc[0][2 * nf2],     a0r, br[0], br[1]);
                    MMA_BF16(acc[0][2 * nf2 + 1], a0r, br[2], br[3]);
                    MMA_BF16(acc[1][2 * nf2],     a1r, br[0], br[1]);
                    MMA_BF16(acc[1][2 * nf2 + 1], a1r, br[2], br[3]);
                }
            }
        }
    }

    // ---- epilogue: c-frag (m = lane/4 + {0,8}, n = 2*(lane%4) + {0,1}) ----
    int rbase = tile * 128 + warp_m + (lane >> 2);
    int cbase = warp_n + (lane & 3) * 2;
    #pragma unroll
    for (int mf = 0; mf < 2; mf++) {
        #pragma unroll
        for (int nf = 0; nf < 8; nf++) {
            int r0 = rbase + mf * 16;
            int c  = cbase + nf * 8;
            if (r0 < n_dst) {
                float2* p = reinterpret_cast<float2*>(out + (size_t)r0 * DFEAT + c);
                *p = make_float2(acc[mf][nf][0], acc[mf][nf][1]);
            }
            if (r0 + 8 < n_dst) {
                float2* p = reinterpret_cast<float2*>(out + (size_t)(r0 + 8) * DFEAT + c);
                *p = make_float2(acc[mf][nf][2], acc[mf][nf][3]);
            }
        }
    }
}

// ============================================================================
// kernel_launch
// inputs: 0:x [N_SRC*128 f32]  1:W1 [128*128 f32]  2:W2 [128*128 f32]
//         3:degree [N_DST f32] 4:src_idx [N_EDGE i32] 5:dst_idx [N_EDGE i32]
//         6:self_ids [N_DST i32]       output: [N_DST*128 f32]
// ============================================================================
extern "C" void kernel_launch(void* const* d_in, const int* in_sizes, int n_in,
                              void* d_out, int out_size) {
    const float* x        = (const float*)d_in[0];
    const float* W1       = (const float*)d_in[1];
    const float* W2       = (const float*)d_in[2];
    const float* degree   = (const float*)d_in[3];
    const int*   src_idx  = (const int*)d_in[4];
    const int*   dst_idx  = (const int*)d_in[5];
    const int*   self_ids = (const int*)d_in[6];
    float* out = (float*)d_out;

    int n_dst  = in_sizes[3];
    int n_edge = in_sizes[4];

    // K0: zero agg
    int n4 = n_dst * (DFEAT / 4);
    zero_agg_kernel<<<(n4 + 255) / 256, 256>>>(n4);

    // K1: scatter edges (1 warp/edge)
    long long tot = (long long)n_edge * 32;
    scatter_kernel<<<(int)((tot + 255) / 256), 256>>>(x, src_idx, dst_idx, n_edge);

    // K2: fused GEMM
    static bool attr_set = false;
    if (!attr_set) {
        cudaFuncSetAttribute(fused_gemm_kernel,
                             cudaFuncAttributeMaxDynamicSharedMemorySize, SMEM_TOTAL);
        attr_set = true;
    }
    fused_gemm_kernel<<<(n_dst + 127) / 128, 256, SMEM_TOTAL>>>(
        x, W1, W2, degree, self_ids, out, n_dst);
}

// round 4
// speedup vs baseline: 1.1457x; 1.1457x over previous
#include <cuda_runtime.h>
#include <cuda_bf16.h>
#include <cstdint>

// ============================================================================
// Problem constants
// ============================================================================
#define DFEAT 128
#define N_DST_MAX 100000
#define N_EDGE_MAX 512000

// static device scratch (no allocations allowed)
__device__ __align__(16) float g_agg[(size_t)N_DST_MAX * DFEAT];  // normalized agg
__device__ int g_cnt[N_DST_MAX];
__device__ int g_rowptr[N_DST_MAX];
__device__ int g_cursor[N_DST_MAX];
__device__ int g_csr[N_EDGE_MAX];
__device__ int g_bsums[64];

// ============================================================================
// Helpers
// ============================================================================
__device__ __forceinline__ uint32_t smem_to_u32(const void* smem_ptr) {
    uint32_t addr;
    asm("{ .reg .u64 tmp; cvta.to.shared.u64 tmp, %1; cvt.u32.u64 %0, tmp; }"
        : "=r"(addr) : "l"(smem_ptr));
    return addr;
}

#define LDSM_X4(r, addr) \
    asm volatile("ldmatrix.sync.aligned.m8n8.x4.shared.b16 {%0,%1,%2,%3}, [%4];" \
        : "=r"((r)[0]), "=r"((r)[1]), "=r"((r)[2]), "=r"((r)[3]) : "r"(addr))

#define MMA_BF16(d, a, b0, b1) \
    asm volatile("mma.sync.aligned.m16n8k16.row.col.f32.bf16.bf16.f32 " \
        "{%0,%1,%2,%3}, {%4,%5,%6,%7}, {%8,%9}, {%0,%1,%2,%3};" \
        : "+f"((d)[0]), "+f"((d)[1]), "+f"((d)[2]), "+f"((d)[3]) \
        : "r"((a)[0]), "r"((a)[1]), "r"((a)[2]), "r"((a)[3]), "r"(b0), "r"(b1))

__device__ __forceinline__ void split2(float f0, float f1, uint32_t& hi, uint32_t& lo) {
    __nv_bfloat16 h0 = __float2bfloat16(f0);
    __nv_bfloat16 h1 = __float2bfloat16(f1);
    __nv_bfloat16 l0 = __float2bfloat16(f0 - __bfloat162float(h0));
    __nv_bfloat16 l1 = __float2bfloat16(f1 - __bfloat162float(h1));
    hi = ((uint32_t)__bfloat16_as_ushort(h1) << 16) | (uint32_t)__bfloat16_as_ushort(h0);
    lo = ((uint32_t)__bfloat16_as_ushort(l1) << 16) | (uint32_t)__bfloat16_as_ushort(l0);
}

// ============================================================================
// CSR build: histogram -> scan -> fill
// ============================================================================
__global__ void zero_cnt_kernel(int n) {
    int i = blockIdx.x * blockDim.x + threadIdx.x;
    if (i < n) g_cnt[i] = 0;
}

__global__ void hist_kernel(const int* __restrict__ dst_idx, int n_edge) {
    int e = blockIdx.x * blockDim.x + threadIdx.x;
    if (e < n_edge) atomicAdd(&g_cnt[__ldg(dst_idx + e)], 1);
}

// exclusive scan over g_cnt -> g_rowptr, block partials into g_bsums.
// 1024 threads, 4 elems/thread => 4096 per block.
__global__ void __launch_bounds__(1024) scan_block_kernel(int n) {
    __shared__ int ssum[1024];
    int b = blockIdx.x, t = threadIdx.x;
    int base = b * 4096 + t * 4;
    int v[4], s = 0;
    #pragma unroll
    for (int j = 0; j < 4; j++) {
        v[j] = (base + j < n) ? g_cnt[base + j] : 0;
        s += v[j];
    }
    ssum[t] = s;
    __syncthreads();
    #pragma unroll
    for (int off = 1; off < 1024; off <<= 1) {
        int val = (t >= off) ? ssum[t - off] : 0;
        __syncthreads();
        ssum[t] += val;
        __syncthreads();
    }
    int run = ssum[t] - s;  // exclusive prefix of this thread
    #pragma unroll
    for (int j = 0; j < 4; j++) {
        if (base + j < n) g_rowptr[base + j] = run;
        run += v[j];
    }
    if (t == 1023) g_bsums[b] = ssum[1023];
}

// exclusive scan over block sums (<=64), one block of 64 threads
__global__ void __launch_bounds__(64) scan_bsums_kernel(int nblocks) {
    __shared__ int s[64];
    int t = threadIdx.x;
    int v = (t < nblocks) ? g_bsums[t] : 0;
    s[t] = v;
    __syncthreads();
    #pragma unroll
    for (int off = 1; off < 64; off <<= 1) {
        int val = (t >= off) ? s[t - off] : 0;
        __syncthreads();
        s[t] += val;
        __syncthreads();
    }
    if (t < nblocks) g_bsums[t] = s[t] - v;  // exclusive
}

__global__ void add_offsets_kernel(int n) {
    int i = blockIdx.x * blockDim.x + threadIdx.x;
    if (i < n) {
        int v = g_rowptr[i] + g_bsums[i >> 12];
        g_rowptr[i] = v;
        g_cursor[i] = v;
    }
}

__global__ void fill_kernel(const int* __restrict__ src_idx,
                            const int* __restrict__ dst_idx, int n_edge) {
    int e = blockIdx.x * blockDim.x + threadIdx.x;
    if (e < n_edge) {
        int d = __ldg(dst_idx + e);
        int p = atomicAdd(&g_cursor[d], 1);
        g_csr[p] = __ldg(src_idx + e);
    }
}

// ============================================================================
// Aggregation: one warp per dst row, lanes hold a float4 each.
// Writes degree-normalized agg with plain stores (no atomics, no zero pass).
// unroll-4 gather for MLP (mean degree ~5).
// ============================================================================
__global__ void __launch_bounds__(256) agg_kernel(
    const float* __restrict__ x,
    const float* __restrict__ degree,
    int n_dst)
{
    int t = blockIdx.x * blockDim.x + threadIdx.x;
    int r = t >> 5;
    if (r >= n_dst) return;
    int lane = t & 31;
    int start = __ldg(&g_rowptr[r]);
    int c = __ldg(&g_cnt[r]);
    const float4* x4 = reinterpret_cast<const float4*>(x);
    float4 acc = make_float4(0.f, 0.f, 0.f, 0.f);
    int e = start, end = start + c;
    for (; e + 3 < end; e += 4) {
        int s0 = __ldg(&g_csr[e]);
        int s1 = __ldg(&g_csr[e + 1]);
        int s2 = __ldg(&g_csr[e + 2]);
        int s3 = __ldg(&g_csr[e + 3]);
        float4 v0 = __ldg(x4 + (size_t)s0 * 32 + lane);
        float4 v1 = __ldg(x4 + (size_t)s1 * 32 + lane);
        float4 v2 = __ldg(x4 + (size_t)s2 * 32 + lane);
        float4 v3 = __ldg(x4 + (size_t)s3 * 32 + lane);
        acc.x += v0.x + v1.x + v2.x + v3.x;
        acc.y += v0.y + v1.y + v2.y + v3.y;
        acc.z += v0.z + v1.z + v2.z + v3.z;
        acc.w += v0.w + v1.w + v2.w + v3.w;
    }
    for (; e < end; e++) {
        int s0 = __ldg(&g_csr[e]);
        float4 v0 = __ldg(x4 + (size_t)s0 * 32 + lane);
        acc.x += v0.x; acc.y += v0.y; acc.z += v0.z; acc.w += v0.w;
    }
    float inv = 1.0f / __ldg(degree + r);
    acc.x *= inv; acc.y *= inv; acc.z *= inv; acc.w *= inv;
    reinterpret_cast<float4*>(g_agg)[(size_t)r * 32 + lane] = acc;
}

// ============================================================================
// Fused GEMM via mma.sync bf16 + hi/lo 3-term split
//   out[r,:] = agg_norm[r,:] @ W1^T + x[self_ids[r],:] @ W2^T
// CTA: 256 threads (8 warps, 4x2), output tile 128x128, warp tile 32x64.
// ============================================================================
#define ROWPITCH 272
#define TILE_BYTES (128 * ROWPITCH)  // 34816
#define SM_A_HI 0
#define SM_A_LO (TILE_BYTES)
#define SM_B_HI (2 * TILE_BYTES)
#define SM_B_LO (3 * TILE_BYTES)
#define SMEM_TOTAL (4 * TILE_BYTES)  // 139264

__global__ void __launch_bounds__(256, 1) fused_gemm_kernel(
    const float* __restrict__ x,
    const float* __restrict__ W1,
    const float* __restrict__ W2,
    const int* __restrict__ self_ids,
    float* __restrict__ out,
    int n_dst)
{
    extern __shared__ char smem[];
    uint32_t smem_base = smem_to_u32(smem);
    int tid = threadIdx.x;
    int wid = tid >> 5;
    int lane = tid & 31;
    int tile = blockIdx.x;

    int warp_m = (wid & 3) * 32;   // 0,32,64,96
    int warp_n = (wid >> 2) * 64;  // 0,64

    float acc[2][8][4];
    #pragma unroll
    for (int i = 0; i < 2; i++)
        #pragma unroll
        for (int j = 0; j < 8; j++)
            #pragma unroll
            for (int q = 0; q < 4; q++) acc[i][j][q] = 0.f;

    // per-lane ldmatrix base offsets
    uint32_t aoff = (uint32_t)(warp_m + (lane & 15)) * ROWPITCH
                  + ((lane & 16) ? 16u : 0u);
    uint32_t boff = (uint32_t)(warp_n + (lane & 7) + ((lane & 16) ? 8 : 0)) * ROWPITCH
                  + ((lane & 8) ? 16u : 0u);

    int lrow = tid >> 1;
    int lcol = (tid & 1) * 64;

    #pragma unroll
    for (int kb = 0; kb < 2; kb++) {
        if (kb) __syncthreads();

        // ---- load A half-tile (agg_norm for kb=0, x[self] for kb=1) ----
        {
            int r = tile * 128 + lrow;
            const float4* src = nullptr;
            if (r < n_dst) {
                if (kb == 0) {
                    src = reinterpret_cast<const float4*>(g_agg + (size_t)r * DFEAT + lcol);
                } else {
                    int sid = __ldg(self_ids + r);
                    src = reinterpret_cast<const float4*>(x + (size_t)sid * DFEAT + lcol);
                }
            }
            #pragma unroll
            for (int j = 0; j < 16; j++) {
                float4 v = make_float4(0.f, 0.f, 0.f, 0.f);
                if (src) v = __ldg(src + j);
                uint32_t h0, l0, h1, l1;
                split2(v.x, v.y, h0, l0);
                split2(v.z, v.w, h1, l1);
                uint32_t o = (uint32_t)lrow * ROWPITCH + (uint32_t)(lcol + 4 * j) * 2;
                *reinterpret_cast<uint32_t*>(smem + SM_A_HI + o)     = h0;
                *reinterpret_cast<uint32_t*>(smem + SM_A_HI + o + 4) = h1;
                *reinterpret_cast<uint32_t*>(smem + SM_A_LO + o)     = l0;
                *reinterpret_cast<uint32_t*>(smem + SM_A_LO + o + 4) = l1;
            }
        }
        // ---- load B half-tile (W1 for kb=0, W2 for kb=1), layout [n][k] ----
        {
            const float* W = kb ? W2 : W1;
            const float4* src = reinterpret_cast<const float4*>(
                W + (size_t)lrow * DFEAT + lcol);
            #pragma unroll
            for (int j = 0; j < 16; j++) {
                float4 v = __ldg(src + j);
                uint32_t h0, l0, h1, l1;
                split2(v.x, v.y, h0, l0);
                split2(v.z, v.w, h1, l1);
                uint32_t o = (uint32_t)lrow * ROWPITCH + (uint32_t)(lcol + 4 * j) * 2;
                *reinterpret_cast<uint32_t*>(smem + SM_B_HI + o)     = h0;
                *reinterpret_cast<uint32_t*>(smem + SM_B_HI + o + 4) = h1;
                *reinterpret_cast<uint32_t*>(smem + SM_B_LO + o)     = l0;
                *reinterpret_cast<uint32_t*>(smem + SM_B_LO + o + 4) = l1;
            }
        }
        __syncthreads();

        // ---- 3 passes x 8 k-steps of mma ----
        #pragma unroll
        for (int p = 0; p < 3; p++) {
            uint32_t abase = smem_base + (p == 1 ? SM_A_LO : SM_A_HI) + aoff;
            uint32_t bbase = smem_base + (p == 2 ? SM_B_LO : SM_B_HI) + boff;
            #pragma unroll
            for (int ks = 0; ks < 8; ks++) {
                uint32_t a0r[4], a1r[4];
                LDSM_X4(a0r, abase + ks * 32);
                LDSM_X4(a1r, abase + 16 * ROWPITCH + ks * 32);
                #pragma unroll
                for (int nf2 = 0; nf2 < 4; nf2++) {
                    uint32_t br[4];
                    LDSM_X4(br, bbase + nf2 * 16 * ROWPITCH + ks * 32);
                    MMA_BF16(acc[0][2 * nf2],     a0r, br[0], br[1]);
                    MMA_BF16(acc[0][2 * nf2 + 1], a0r, br[2], br[3]);
                    MMA_BF16(acc[1][2 * nf2],     a1r, br[0], br[1]);
                    MMA_BF16(acc[1][2 * nf2 + 1], a1r, br[2], br[3]);
                }
            }
        }
    }

    // ---- epilogue ----
    int rbase = tile * 128 + warp_m + (lane >> 2);
    int cbase = warp_n + (lane & 3) * 2;
    #pragma unroll
    for (int mf = 0; mf < 2; mf++) {
        #pragma unroll
        for (int nf = 0; nf < 8; nf++) {
            int r0 = rbase + mf * 16;
            int c  = cbase + nf * 8;
            if (r0 < n_dst) {
                float2* p = reinterpret_cast<float2*>(out + (size_t)r0 * DFEAT + c);
                *p = make_float2(acc[mf][nf][0], acc[mf][nf][1]);
            }
            if (r0 + 8 < n_dst) {
                float2* p = reinterpret_cast<float2*>(out + (size_t)(r0 + 8) * DFEAT + c);
                *p = make_float2(acc[mf][nf][2], acc[mf][nf][3]);
            }
        }
    }
}

// ============================================================================
// kernel_launch
// inputs: 0:x [N_SRC*128 f32]  1:W1 [128*128 f32]  2:W2 [128*128 f32]
//         3:degree [N_DST f32] 4:src_idx [N_EDGE i32] 5:dst_idx [N_EDGE i32]
//         6:self_ids [N_DST i32]       output: [N_DST*128 f32]
// ============================================================================
extern "C" void kernel_launch(void* const* d_in, const int* in_sizes, int n_in,
                              void* d_out, int out_size) {
    const float* x        = (const float*)d_in[0];
    const float* W1       = (const float*)d_in[1];
    const float* W2       = (const float*)d_in[2];
    const float* degree   = (const float*)d_in[3];
    const int*   src_idx  = (const int*)d_in[4];
    const int*   dst_idx  = (const int*)d_in[5];
    const int*   self_ids = (const int*)d_in[6];
    float* out = (float*)d_out;

    int n_dst  = in_sizes[3];
    int n_edge = in_sizes[4];

    // CSR build
    zero_cnt_kernel<<<(n_dst + 255) / 256, 256>>>(n_dst);
    hist_kernel<<<(n_edge + 255) / 256, 256>>>(dst_idx, n_edge);
    int nblocks = (n_dst + 4095) / 4096;
    scan_block_kernel<<<nblocks, 1024>>>(n_dst);
    scan_bsums_kernel<<<1, 64>>>(nblocks);
    add_offsets_kernel<<<(n_dst + 255) / 256, 256>>>(n_dst);
    fill_kernel<<<(n_edge + 255) / 256, 256>>>(src_idx, dst_idx, n_edge);

    // Aggregation (1 warp / dst row)
    long long tot = (long long)n_dst * 32;
    agg_kernel<<<(int)((tot + 255) / 256), 256>>>(x, degree, n_dst);

    // Fused GEMM
    static bool attr_set = false;
    if (!attr_set) {
        cudaFuncSetAttribute(fused_gemm_kernel,
                             cudaFuncAttributeMaxDynamicSharedMemorySize, SMEM_TOTAL);
        attr_set = true;
    }
    fused_gemm_kernel<<<(n_dst + 127) / 128, 256, SMEM_TOTAL>>>(
        x, W1, W2, self_ids, out, n_dst);
}